// round 3
// baseline (speedup 1.0000x reference)
#include <cuda_runtime.h>

#define BATCH 16
#define CH 512
#define HWN 4096
#define NHEADS 8
#define HD 64

// Scratch (device globals — no allocation allowed in kernel_launch)
__device__ float g_k[(size_t)BATCH * CH * HWN];
__device__ float g_q[(size_t)BATCH * CH * HWN];
__device__ float g_v[(size_t)BATCH * CH * HWN];
__device__ float g_ctx[BATCH * NHEADS * HD * HD];
__device__ float g_weff[(size_t)BATCH * CH * CH];

// ---------------------------------------------------------------------------
// Batched SGEMM with bias: out[b] = A(b) @ X[b] + bias
// A: [512, 512] row-major (per-batch stride a_bstride; 0 => shared weights)
// X: [512, 4096] per batch, out: [512, 4096] per batch.
// 128x128 tile, BK=8, 256 threads, 8x8 per thread.
// ---------------------------------------------------------------------------
__global__ __launch_bounds__(256) void sgemm_bias(
    const float* __restrict__ A, long a_bstride,
    const float* __restrict__ X,
    const float* __restrict__ bias,
    float* __restrict__ out)
{
    const int K = CH, N = HWN;
    const int b = blockIdx.z;
    A   += (long)b * a_bstride;
    X   += (long)b * (long)K * N;
    out += (long)b * (long)CH * N;

    const int m0 = blockIdx.y * 128;
    const int n0 = blockIdx.x * 128;

    __shared__ float As[8][128];
    __shared__ float Bs[8][128];

    const int t  = threadIdx.x;
    const int tx = t & 15;      // column group
    const int ty = t >> 4;      // row group

    float acc[8][8];
#pragma unroll
    for (int i = 0; i < 8; i++)
#pragma unroll
        for (int j = 0; j < 8; j++) acc[i][j] = 0.f;

    // load assignments (float4 per thread per tile)
    const int ar = t >> 1;            // 0..127  (A row within tile)
    const int ac = (t & 1) * 4;       // 0 or 4  (A col within tile)
    const int brw = t >> 5;           // 0..7    (B row within tile)
    const int bcl = (t & 31) * 4;     // 0..124  (B col within tile)

    for (int k0 = 0; k0 < K; k0 += 8) {
        float4 av = *reinterpret_cast<const float4*>(&A[(long)(m0 + ar) * K + k0 + ac]);
        As[ac + 0][ar] = av.x;
        As[ac + 1][ar] = av.y;
        As[ac + 2][ar] = av.z;
        As[ac + 3][ar] = av.w;
        float4 bv = *reinterpret_cast<const float4*>(&X[(long)(k0 + brw) * N + n0 + bcl]);
        *reinterpret_cast<float4*>(&Bs[brw][bcl]) = bv;
        __syncthreads();

#pragma unroll
        for (int kk = 0; kk < 8; kk++) {
            float a[8], bb[8];
#pragma unroll
            for (int i = 0; i < 8; i++) a[i] = As[kk][ty * 8 + i];
#pragma unroll
            for (int j = 0; j < 8; j++) bb[j] = Bs[kk][tx * 8 + j];
#pragma unroll
            for (int i = 0; i < 8; i++)
#pragma unroll
                for (int j = 0; j < 8; j++)
                    acc[i][j] += a[i] * bb[j];
        }
        __syncthreads();
    }

#pragma unroll
    for (int i = 0; i < 8; i++) {
        const int m = m0 + ty * 8 + i;
        const float bs = bias[m];
        float4 v0 = make_float4(acc[i][0] + bs, acc[i][1] + bs, acc[i][2] + bs, acc[i][3] + bs);
        float4 v1 = make_float4(acc[i][4] + bs, acc[i][5] + bs, acc[i][6] + bs, acc[i][7] + bs);
        float* op = &out[(long)m * N + n0 + tx * 8];
        *reinterpret_cast<float4*>(op)     = v0;
        *reinterpret_cast<float4*>(op + 4) = v1;
    }
}

// ---------------------------------------------------------------------------
// Softmax over the spatial axis (4096) — one block per (b, channel) row.
// ---------------------------------------------------------------------------
__global__ __launch_bounds__(256) void softmax_spatial(float* __restrict__ data)
{
    const long row = blockIdx.x;
    float* p = data + row * (long)HWN;
    const int t = threadIdx.x;

    __shared__ float redmax[8];
    __shared__ float redsum[8];

    float vals[16];
    float mx = -1e30f;
#pragma unroll
    for (int i = 0; i < 16; i++) {
        vals[i] = p[t + 256 * i];
        mx = fmaxf(mx, vals[i]);
    }
#pragma unroll
    for (int off = 16; off; off >>= 1)
        mx = fmaxf(mx, __shfl_xor_sync(0xffffffffu, mx, off));
    if ((t & 31) == 0) redmax[t >> 5] = mx;
    __syncthreads();
    float bm = redmax[0];
#pragma unroll
    for (int w = 1; w < 8; w++) bm = fmaxf(bm, redmax[w]);

    float s = 0.f;
#pragma unroll
    for (int i = 0; i < 16; i++) {
        vals[i] = __expf(vals[i] - bm);
        s += vals[i];
    }
#pragma unroll
    for (int off = 16; off; off >>= 1)
        s += __shfl_xor_sync(0xffffffffu, s, off);
    if ((t & 31) == 0) redsum[t >> 5] = s;
    __syncthreads();
    float tot = 0.f;
#pragma unroll
    for (int w = 0; w < 8; w++) tot += redsum[w];
    const float inv = 1.f / tot;

#pragma unroll
    for (int i = 0; i < 16; i++)
        p[t + 256 * i] = vals[i] * inv;
}

// ---------------------------------------------------------------------------
// Softmax over the per-head channel axis (64) for q.
// One thread per (b, h, l); loads are coalesced across l.
// ---------------------------------------------------------------------------
__global__ __launch_bounds__(256) void softmax_channel(float* __restrict__ q)
{
    const int idx = blockIdx.x * 256 + threadIdx.x;   // B * NHEADS * HWN
    const int l  = idx & (HWN - 1);
    const int bh = idx >> 12;
    const int h  = bh & (NHEADS - 1);
    const int b  = bh >> 3;
    float* base = q + ((long)b * CH + (long)h * HD) * HWN + l;

    float v[HD];
    float mx = -1e30f;
#pragma unroll
    for (int c = 0; c < HD; c++) {
        v[c] = base[(long)c * HWN];
        mx = fmaxf(mx, v[c]);
    }
    float s = 0.f;
#pragma unroll
    for (int c = 0; c < HD; c++) {
        v[c] = __expf(v[c] - mx);
        s += v[c];
    }
    const float inv = 1.f / s;
#pragma unroll
    for (int c = 0; c < HD; c++)
        base[(long)c * HWN] = v[c] * inv;
}

// ---------------------------------------------------------------------------
// ctx[b,h] = k_soft[b,h] @ v[b,h]^T  : [64, 4096] x [64, 4096]^T -> [64, 64]
// One block per (b,h). SMEM-tiled over the spatial axis.
// ---------------------------------------------------------------------------
__global__ __launch_bounds__(256) void ctx_kernel()
{
    const int bh = blockIdx.x;                       // 0..127
    const float* kp = g_k + (long)bh * HD * HWN;     // CH = NHEADS*HD so contiguous
    const float* vp = g_v + (long)bh * HD * HWN;

    __shared__ float ks[64][65];
    __shared__ float vs[64][65];

    const int t  = threadIdx.x;
    const int tx = t & 15, ty = t >> 4;
    float acc[4][4] = {};

    for (int l0 = 0; l0 < HWN; l0 += 64) {
#pragma unroll
        for (int r = 0; r < 16; r++) {
            const int idx = t + r * 256;
            const int row = idx >> 6, col = idx & 63;
            ks[row][col] = kp[(long)row * HWN + l0 + col];
            vs[row][col] = vp[(long)row * HWN + l0 + col];
        }
        __syncthreads();
#pragma unroll
        for (int ll = 0; ll < 64; ll++) {
            float a[4], bb[4];
#pragma unroll
            for (int i = 0; i < 4; i++) a[i] = ks[ty * 4 + i][ll];
#pragma unroll
            for (int j = 0; j < 4; j++) bb[j] = vs[tx * 4 + j][ll];
#pragma unroll
            for (int i = 0; i < 4; i++)
#pragma unroll
                for (int j = 0; j < 4; j++)
                    acc[i][j] += a[i] * bb[j];
        }
        __syncthreads();
    }

    float* cp = g_ctx + (long)bh * HD * HD;
#pragma unroll
    for (int i = 0; i < 4; i++)
#pragma unroll
        for (int j = 0; j < 4; j++)
            cp[(ty * 4 + i) * HD + tx * 4 + j] = acc[i][j];
}

// ---------------------------------------------------------------------------
// Weff[b][o][h*64+k] = sum_v Wr[o, h*64+v] * ctx[b,h,k,v]
// Folds the output projection through ctx so the final pass is a plain GEMM
// over q (avoids materializing av entirely).
// ---------------------------------------------------------------------------
__global__ __launch_bounds__(256) void weff_kernel(const float* __restrict__ Wr)
{
    const int idx = blockIdx.x * 256 + threadIdx.x;  // B*CH*CH
    const int col = idx & (CH - 1);
    const int o   = (idx >> 9) & (CH - 1);
    const int b   = idx >> 18;
    const int h   = col >> 6;
    const int kk  = col & 63;

    const float* wr = Wr + (long)o * CH + h * HD;
    const float* cx = g_ctx + ((long)(b * NHEADS + h) * HD + kk) * HD;
    float s = 0.f;
#pragma unroll
    for (int vv = 0; vv < HD; vv++)
        s += wr[vv] * cx[vv];
    g_weff[idx] = s;
}

// ---------------------------------------------------------------------------
extern "C" void kernel_launch(void* const* d_in, const int* in_sizes, int n_in,
                              void* d_out, int out_size)
{
    const float* x  = (const float*)d_in[0];
    const float* Wk = (const float*)d_in[1];
    const float* bk = (const float*)d_in[2];
    const float* Wq = (const float*)d_in[3];
    const float* bq = (const float*)d_in[4];
    const float* Wv = (const float*)d_in[5];
    const float* bv = (const float*)d_in[6];
    const float* Wr = (const float*)d_in[7];
    const float* br = (const float*)d_in[8];
    float* out = (float*)d_out;

    float *pk, *pq, *pv, *pweff;
    cudaGetSymbolAddress((void**)&pk,    g_k);
    cudaGetSymbolAddress((void**)&pq,    g_q);
    cudaGetSymbolAddress((void**)&pv,    g_v);
    cudaGetSymbolAddress((void**)&pweff, g_weff);

    dim3 gemm_grid(HWN / 128, CH / 128, BATCH);

    // QKV projections (shared weights across batch: a_bstride = 0)
    sgemm_bias<<<gemm_grid, 256>>>(Wk, 0, x, bk, pk);
    sgemm_bias<<<gemm_grid, 256>>>(Wq, 0, x, bq, pq);
    sgemm_bias<<<gemm_grid, 256>>>(Wv, 0, x, bv, pv);

    // Softmaxes
    softmax_spatial<<<BATCH * CH, 256>>>(pk);
    softmax_channel<<<(BATCH * NHEADS * HWN) / 256, 256>>>(pq);

    // ctx = k @ v^T per (b, h)
    ctx_kernel<<<BATCH * NHEADS, 256>>>();

    // Fold Wr into ctx -> per-batch effective weight
    weff_kernel<<<(BATCH * CH * CH) / 256, 256>>>(Wr);

    // out[b] = Weff[b] @ q[b] + br
    sgemm_bias<<<gemm_grid, 256>>>(pweff, (long)CH * CH, pq, br, out);
}

// round 7
// speedup vs baseline: 1.6888x; 1.6888x over previous
#include <cuda_runtime.h>
#include <cuda_bf16.h>
#include <cstdint>

typedef __nv_bfloat16 bf16;

#define BATCH 16
#define CH 512
#define HWN 4096
#define NHEADS 8
#define HD 64
#define MQKV (3 * CH)          // 1536 fused output rows for QKV

// GEMM tiling
#define BM 128
#define BN 128
#define BK 16
#define SA 24          // As row stride (bf16 units)  -> 48B, conflict-free ldmatrix
#define SB 136         // Bs row stride (bf16 units)  -> 272B, conflict-free ldmatrix.trans
#define NIT (CH / BK)

// ---------------------------------------------------------------------------
// Scratch (device globals — no allocation allowed)
// g_kqv: fused fp32 [B][1536][4096]; rows 0-511 = k, 512-1023 = q, 1024-1535 = v
// ---------------------------------------------------------------------------
__device__ float g_kqv[(size_t)BATCH * MQKV * HWN];
__device__ float g_ctx[BATCH * NHEADS * HD * HD];
__device__ bf16  g_xh[(size_t)BATCH * CH * HWN];
__device__ bf16  g_xl[(size_t)BATCH * CH * HWN];
__device__ bf16  g_qh[(size_t)BATCH * CH * HWN];
__device__ bf16  g_ql[(size_t)BATCH * CH * HWN];
__device__ bf16  g_wh[MQKV * CH];
__device__ bf16  g_wl[MQKV * CH];
__device__ bf16  g_weffh[(size_t)BATCH * CH * CH];
__device__ bf16  g_weffl[(size_t)BATCH * CH * CH];

// ---------------------------------------------------------------------------
// PTX helpers
// ---------------------------------------------------------------------------
#define CP16(dst_u32, src_ptr) \
    asm volatile("cp.async.cg.shared.global [%0], [%1], 16;\n" :: "r"(dst_u32), "l"(src_ptr))

#define CP_COMMIT() asm volatile("cp.async.commit_group;\n" ::: "memory")
#define CP_WAIT1()  asm volatile("cp.async.wait_group 1;\n"  ::: "memory")
#define CP_WAIT0()  asm volatile("cp.async.wait_group 0;\n"  ::: "memory")

#define LDSM4(R, addr) \
    asm volatile("ldmatrix.sync.aligned.m8n8.x4.shared.b16 {%0,%1,%2,%3}, [%4];" \
        : "=r"((R)[0]), "=r"((R)[1]), "=r"((R)[2]), "=r"((R)[3]) : "r"(addr))

#define LDSM4T(R, addr) \
    asm volatile("ldmatrix.sync.aligned.m8n8.x4.trans.shared.b16 {%0,%1,%2,%3}, [%4];" \
        : "=r"((R)[0]), "=r"((R)[1]), "=r"((R)[2]), "=r"((R)[3]) : "r"(addr))

#define MMA16816(d, a, b0v, b1v) \
    asm volatile("mma.sync.aligned.m16n8k16.row.col.f32.bf16.bf16.f32 " \
        "{%0,%1,%2,%3},{%4,%5,%6,%7},{%8,%9},{%0,%1,%2,%3};" \
        : "+f"((d)[0]), "+f"((d)[1]), "+f"((d)[2]), "+f"((d)[3]) \
        : "r"((a)[0]), "r"((a)[1]), "r"((a)[2]), "r"((a)[3]), "r"(b0v), "r"(b1v))

__device__ __forceinline__ void split_f32(float v, bf16& h, bf16& l) {
    h = __float2bfloat16_rn(v);
    l = __float2bfloat16_rn(v - __bfloat162float(h));
}

// ---------------------------------------------------------------------------
// bf16x3 batched GEMM with bias: out[b] = A(b) @ X[b] + bias
// A_hi/A_lo: [Mtot, 512] bf16 row-major (per-batch stride a_bstride; 0 = shared)
// B_hi/B_lo: [512, 4096] bf16 per batch (stride CH*HWN); out fp32.
// Bias selected per 512-row section (bias0 for rows<512, bias1, bias2).
// 128x128x16 tile, 256 threads (8 warps, 2x4), 64x32 per warp, mma m16n8k16.
// Accumulates Ah*Bh + Ah*Bl + Al*Bh in fp32 (~3e-5 rel err vs fp32).
// ---------------------------------------------------------------------------
__global__ __launch_bounds__(256, 1) void gemm_bf16x3(
    const bf16* __restrict__ Ah, const bf16* __restrict__ Al, long a_bstride,
    const bf16* __restrict__ Bh, const bf16* __restrict__ Bl,
    const float* __restrict__ bias0, const float* __restrict__ bias1,
    const float* __restrict__ bias2,
    long out_bstride, float* __restrict__ out)
{
    __shared__ __align__(16) bf16 sAh[2][BM * SA];
    __shared__ __align__(16) bf16 sAl[2][BM * SA];
    __shared__ __align__(16) bf16 sBh[2][BK * SB];
    __shared__ __align__(16) bf16 sBl[2][BK * SB];

    const int bz = blockIdx.z;
    Ah += (long)bz * a_bstride;
    Al += (long)bz * a_bstride;
    Bh += (long)bz * (long)CH * HWN;
    Bl += (long)bz * (long)CH * HWN;
    out += (long)bz * out_bstride;

    const int m0 = blockIdx.y * BM;
    const int n0 = blockIdx.x * BN;
    const int t = threadIdx.x, lane = t & 31, wid = t >> 5;
    const int wm = (wid >> 2) * 64;      // warp m-offset (0/64)
    const int wn = (wid & 3) * 32;       // warp n-offset

    const uint32_t sAh_b = (uint32_t)__cvta_generic_to_shared(&sAh[0][0]);
    const uint32_t sAl_b = (uint32_t)__cvta_generic_to_shared(&sAl[0][0]);
    const uint32_t sBh_b = (uint32_t)__cvta_generic_to_shared(&sBh[0][0]);
    const uint32_t sBl_b = (uint32_t)__cvta_generic_to_shared(&sBl[0][0]);
    const uint32_t ASTG = BM * SA * 2;   // bytes per stage (per array)
    const uint32_t BSTG = BK * SB * 2;

    // ---- staging descriptors (each thread: 2 A chunks + 2 B chunks of 16B) ----
    const int  rowA = t >> 2, subA = t & 3;
    const bf16* srcA = ((subA & 2) ? Al : Ah) + (long)(m0 + rowA) * CH + (subA & 1) * 8;
    const uint32_t dstAbase = ((subA & 2) ? sAl_b : sAh_b);
    const uint32_t dstAoff = (uint32_t)(rowA * SA + (subA & 1) * 8) * 2;
    const int  krB = t >> 5, subB = t & 31;
    const bf16* srcB = ((subB & 16) ? Bl : Bh) + (long)krB * HWN + n0 + (subB & 15) * 8;
    const uint32_t dstBbase = ((subB & 16) ? sBl_b : sBh_b);
    const uint32_t dstBoff = (uint32_t)(krB * SB + (subB & 15) * 8) * 2;

    // ---- ldmatrix lane offsets (bf16 units) ----
    const int a_lm = (lane % 16) * SA + (lane / 16) * 8;
    const int b_lm = (lane % 16) * SB + (lane / 16) * 8;

    float acc[4][4][4];
#pragma unroll
    for (int i = 0; i < 4; i++)
#pragma unroll
        for (int j = 0; j < 4; j++)
#pragma unroll
            for (int r = 0; r < 4; r++) acc[i][j][r] = 0.f;

    // prologue: stage 0
    {
        CP16(dstAbase + dstAoff, srcA);
        CP16(dstAbase + dstAoff + 64 * SA * 2, srcA + 64 * CH);
        CP16(dstBbase + dstBoff, srcB);
        CP16(dstBbase + dstBoff + 8 * SB * 2, srcB + 8 * (long)HWN);
        CP_COMMIT();
    }

    for (int it = 0; it < NIT; ++it) {
        const int s = it & 1;
        if (it + 1 < NIT) {
            const int k0 = (it + 1) * BK;
            const uint32_t so = (uint32_t)(s ^ 1);
            CP16(dstAbase + so * ASTG + dstAoff, srcA + k0);
            CP16(dstAbase + so * ASTG + dstAoff + 64 * SA * 2, srcA + 64 * CH + k0);
            CP16(dstBbase + so * BSTG + dstBoff, srcB + (long)k0 * HWN);
            CP16(dstBbase + so * BSTG + dstBoff + 8 * SB * 2, srcB + (long)(k0 + 8) * HWN);
            CP_COMMIT();
            CP_WAIT1();
        } else {
            CP_WAIT0();
        }
        __syncthreads();

        uint32_t ah[4][4], al[4][4], bh[2][4], bl[2][4];
#pragma unroll
        for (int mt = 0; mt < 4; mt++) {
            const uint32_t ao = s * ASTG + (uint32_t)((wm + mt * 16) * SA + a_lm) * 2;
            LDSM4(ah[mt], sAh_b + ao);
            LDSM4(al[mt], sAl_b + ao);
        }
#pragma unroll
        for (int gi = 0; gi < 2; gi++) {
            const uint32_t bo = s * BSTG + (uint32_t)(b_lm + wn + gi * 16) * 2;
            LDSM4T(bh[gi], sBh_b + bo);
            LDSM4T(bl[gi], sBl_b + bo);
        }

#pragma unroll
        for (int mt = 0; mt < 4; mt++)
#pragma unroll
            for (int nt = 0; nt < 4; nt++) {
                const int gi = nt >> 1, p = (nt & 1) * 2;
                MMA16816(acc[mt][nt], ah[mt], bh[gi][p], bh[gi][p + 1]);
                MMA16816(acc[mt][nt], ah[mt], bl[gi][p], bl[gi][p + 1]);
                MMA16816(acc[mt][nt], al[mt], bh[gi][p], bh[gi][p + 1]);
            }
        __syncthreads();
    }

    // ---- epilogue: per-section bias + fp32 store ----
    const int gq = lane >> 2, tq = lane & 3;
#pragma unroll
    for (int mt = 0; mt < 4; mt++) {
        const int m = m0 + wm + mt * 16 + gq;
        // both m and m+8 are in the same 512-row section (section size % 128 == 0)
        const float* bs = (m < CH) ? bias0 : (m < 2 * CH) ? bias1 : bias2;
        const float b0v = bs[m & (CH - 1)], b1v = bs[(m + 8) & (CH - 1)];
#pragma unroll
        for (int nt = 0; nt < 4; nt++) {
            const int n = n0 + wn + nt * 8 + tq * 2;
            float2 v0 = make_float2(acc[mt][nt][0] + b0v, acc[mt][nt][1] + b0v);
            float2 v1 = make_float2(acc[mt][nt][2] + b1v, acc[mt][nt][3] + b1v);
            *reinterpret_cast<float2*>(&out[(long)m * HWN + n]) = v0;
            *reinterpret_cast<float2*>(&out[(long)(m + 8) * HWN + n]) = v1;
        }
    }
}

// ---------------------------------------------------------------------------
// fp32 -> bf16 hi/lo split (float4 per thread)
// ---------------------------------------------------------------------------
__global__ __launch_bounds__(256) void split_kernel(
    const float* __restrict__ in, bf16* __restrict__ hi, bf16* __restrict__ lo, int n4)
{
    const int i = blockIdx.x * 256 + threadIdx.x;
    if (i >= n4) return;
    float4 v = reinterpret_cast<const float4*>(in)[i];
    bf16 h0, h1, h2, h3, l0, l1, l2, l3;
    split_f32(v.x, h0, l0);
    split_f32(v.y, h1, l1);
    split_f32(v.z, h2, l2);
    split_f32(v.w, h3, l3);
    __nv_bfloat162* hp = reinterpret_cast<__nv_bfloat162*>(hi) + 2 * i;
    __nv_bfloat162* lp = reinterpret_cast<__nv_bfloat162*>(lo) + 2 * i;
    hp[0] = __nv_bfloat162(h0, h1);
    hp[1] = __nv_bfloat162(h2, h3);
    lp[0] = __nv_bfloat162(l0, l1);
    lp[1] = __nv_bfloat162(l2, l3);
}

// ---------------------------------------------------------------------------
// Softmax over the spatial axis (4096) for the k section of g_kqv.
// blockIdx.x = b * CH + c.
// ---------------------------------------------------------------------------
__global__ __launch_bounds__(256) void softmax_spatial()
{
    const int b = blockIdx.x >> 9;
    const int c = blockIdx.x & (CH - 1);
    float* p = g_kqv + ((long)b * MQKV + c) * HWN;
    const int t = threadIdx.x;

    __shared__ float redmax[8];
    __shared__ float redsum[8];

    float vals[16];
    float mx = -1e30f;
#pragma unroll
    for (int i = 0; i < 16; i++) {
        vals[i] = p[t + 256 * i];
        mx = fmaxf(mx, vals[i]);
    }
#pragma unroll
    for (int off = 16; off; off >>= 1)
        mx = fmaxf(mx, __shfl_xor_sync(0xffffffffu, mx, off));
    if ((t & 31) == 0) redmax[t >> 5] = mx;
    __syncthreads();
    float bm = redmax[0];
#pragma unroll
    for (int w = 1; w < 8; w++) bm = fmaxf(bm, redmax[w]);

    float s = 0.f;
#pragma unroll
    for (int i = 0; i < 16; i++) {
        vals[i] = __expf(vals[i] - bm);
        s += vals[i];
    }
#pragma unroll
    for (int off = 16; off; off >>= 1)
        s += __shfl_xor_sync(0xffffffffu, s, off);
    if ((t & 31) == 0) redsum[t >> 5] = s;
    __syncthreads();
    float tot = 0.f;
#pragma unroll
    for (int w = 0; w < 8; w++) tot += redsum[w];
    const float inv = 1.f / tot;

#pragma unroll
    for (int i = 0; i < 16; i++)
        p[t + 256 * i] = vals[i] * inv;
}

// ---------------------------------------------------------------------------
// Softmax over the per-head channel axis (64) for the q section of g_kqv;
// emits bf16 hi/lo split into g_qh/g_ql ([B,512,4096] layout).
// ---------------------------------------------------------------------------
__global__ __launch_bounds__(256) void softmax_channel_split(
    bf16* __restrict__ qh, bf16* __restrict__ ql)
{
    const int idx = blockIdx.x * 256 + threadIdx.x;   // B * NHEADS * HWN
    const int l  = idx & (HWN - 1);
    const int bh = idx >> 12;
    const int h  = bh & (NHEADS - 1);
    const int b  = bh >> 3;
    const float* src = g_kqv + ((long)b * MQKV + CH + (long)h * HD) * HWN + l;
    const long dst = ((long)b * CH + (long)h * HD) * HWN + l;

    float v[HD];
    float mx = -1e30f;
#pragma unroll
    for (int c = 0; c < HD; c++) {
        v[c] = src[(long)c * HWN];
        mx = fmaxf(mx, v[c]);
    }
    float s = 0.f;
#pragma unroll
    for (int c = 0; c < HD; c++) {
        v[c] = __expf(v[c] - mx);
        s += v[c];
    }
    const float inv = 1.f / s;
#pragma unroll
    for (int c = 0; c < HD; c++) {
        bf16 hh, ll;
        split_f32(v[c] * inv, hh, ll);
        qh[dst + (long)c * HWN] = hh;
        ql[dst + (long)c * HWN] = ll;
    }
}

// ---------------------------------------------------------------------------
// ctx[b,h] = k_soft[b,h] @ v[b,h]^T  : [64,4096] x [64,4096]^T -> [64,64]
// ---------------------------------------------------------------------------
__global__ __launch_bounds__(256) void ctx_kernel()
{
    const int bh = blockIdx.x;                       // 0..127
    const int b = bh >> 3, h = bh & (NHEADS - 1);
    const float* kp = g_kqv + ((long)b * MQKV + (long)h * HD) * HWN;
    const float* vp = g_kqv + ((long)b * MQKV + 2 * CH + (long)h * HD) * HWN;

    __shared__ float ks[64][65];
    __shared__ float vs[64][65];

    const int t  = threadIdx.x;
    const int tx = t & 15, ty = t >> 4;
    float acc[4][4] = {};

    for (int l0 = 0; l0 < HWN; l0 += 64) {
#pragma unroll
        for (int r = 0; r < 16; r++) {
            const int idx = t + r * 256;
            const int row = idx >> 6, col = idx & 63;
            ks[row][col] = kp[(long)row * HWN + l0 + col];
            vs[row][col] = vp[(long)row * HWN + l0 + col];
        }
        __syncthreads();
#pragma unroll
        for (int ll = 0; ll < 64; ll++) {
            float a[4], bb[4];
#pragma unroll
            for (int i = 0; i < 4; i++) a[i] = ks[ty * 4 + i][ll];
#pragma unroll
            for (int j = 0; j < 4; j++) bb[j] = vs[tx * 4 + j][ll];
#pragma unroll
            for (int i = 0; i < 4; i++)
#pragma unroll
                for (int j = 0; j < 4; j++)
                    acc[i][j] += a[i] * bb[j];
        }
        __syncthreads();
    }

    float* cp = g_ctx + (long)bh * HD * HD;
#pragma unroll
    for (int i = 0; i < 4; i++)
#pragma unroll
        for (int j = 0; j < 4; j++)
            cp[(ty * 4 + i) * HD + tx * 4 + j] = acc[i][j];
}

// ---------------------------------------------------------------------------
// Weff[b][o][h*64+k] = sum_v Wr[o, h*64+v] * ctx[b,h,k,v]  -> bf16 hi/lo
// ---------------------------------------------------------------------------
__global__ __launch_bounds__(256) void weff_split(const float* __restrict__ Wr)
{
    const int idx = blockIdx.x * 256 + threadIdx.x;  // B*CH*CH
    const int col = idx & (CH - 1);
    const int o   = (idx >> 9) & (CH - 1);
    const int b   = idx >> 18;
    const int h   = col >> 6;
    const int kk  = col & 63;

    const float* wr = Wr + (long)o * CH + h * HD;
    const float* cx = g_ctx + ((long)(b * NHEADS + h) * HD + kk) * HD;
    float s = 0.f;
#pragma unroll
    for (int vv = 0; vv < HD; vv++)
        s += wr[vv] * cx[vv];
    bf16 hh, ll;
    split_f32(s, hh, ll);
    g_weffh[idx] = hh;
    g_weffl[idx] = ll;
}

// ---------------------------------------------------------------------------
extern "C" void kernel_launch(void* const* d_in, const int* in_sizes, int n_in,
                              void* d_out, int out_size)
{
    const float* x  = (const float*)d_in[0];
    const float* Wk = (const float*)d_in[1];
    const float* bk = (const float*)d_in[2];
    const float* Wq = (const float*)d_in[3];
    const float* bq = (const float*)d_in[4];
    const float* Wv = (const float*)d_in[5];
    const float* bv = (const float*)d_in[6];
    const float* Wr = (const float*)d_in[7];
    const float* br = (const float*)d_in[8];
    float* out = (float*)d_out;

    float *pkqv;
    bf16 *pxh, *pxl, *pqh, *pql, *pwh, *pwl, *pweh, *pwel;
    cudaGetSymbolAddress((void**)&pkqv, g_kqv);
    cudaGetSymbolAddress((void**)&pxh,  g_xh);
    cudaGetSymbolAddress((void**)&pxl,  g_xl);
    cudaGetSymbolAddress((void**)&pqh,  g_qh);
    cudaGetSymbolAddress((void**)&pql,  g_ql);
    cudaGetSymbolAddress((void**)&pwh,  g_wh);
    cudaGetSymbolAddress((void**)&pwl,  g_wl);
    cudaGetSymbolAddress((void**)&pweh, g_weffh);
    cudaGetSymbolAddress((void**)&pwel, g_weffl);

    const int WN4 = CH * CH / 4;              // float4 per 512x512 weight
    const int XN4 = BATCH * CH * HWN / 4;

    // Split weights (stacked [Wk;Wq;Wv]) and x into bf16 hi/lo
    split_kernel<<<WN4 / 256, 256>>>(Wk, pwh + 0 * CH * CH, pwl + 0 * CH * CH, WN4);
    split_kernel<<<WN4 / 256, 256>>>(Wq, pwh + 1 * CH * CH, pwl + 1 * CH * CH, WN4);
    split_kernel<<<WN4 / 256, 256>>>(Wv, pwh + 2 * CH * CH, pwl + 2 * CH * CH, WN4);
    split_kernel<<<XN4 / 256, 256>>>(x, pxh, pxl, XN4);

    // Fused QKV projection: [1536,512] @ [512,4096] per batch (x read once)
    dim3 qkv_grid(HWN / BN, MQKV / BM, BATCH);
    gemm_bf16x3<<<qkv_grid, 256>>>(pwh, pwl, 0, pxh, pxl,
                                   bk, bq, bv, (long)MQKV * HWN, pkqv);

    // Softmaxes
    softmax_spatial<<<BATCH * CH, 256>>>();
    softmax_channel_split<<<(BATCH * NHEADS * HWN) / 256, 256>>>(pqh, pql);

    // ctx = k @ v^T per (b, h)
    ctx_kernel<<<BATCH * NHEADS, 256>>>();

    // Fold Wr through ctx -> per-batch effective weight (bf16 hi/lo)
    weff_split<<<(BATCH * CH * CH) / 256, 256>>>(Wr);

    // out[b] = Weff[b] @ q[b] + br
    dim3 out_grid(HWN / BN, CH / BM, BATCH);
    gemm_bf16x3<<<out_grid, 256>>>(pweh, pwel, (long)CH * CH, pqh, pql,
                                   br, br, br, (long)CH * HWN, out);
}

// round 13
// speedup vs baseline: 1.8336x; 1.0857x over previous
#include <cuda_runtime.h>
#include <cuda_bf16.h>
#include <cstdint>

typedef __nv_bfloat16 bf16;

#define BATCH 16
#define CH 512
#define HWN 4096
#define NHEADS 8
#define HD 64
#define MQKV (3 * CH)          // 1536 fused output rows for QKV

// GEMM tiling: 128x128 CTA tile, BK=32 slab, 3-stage cp.async pipeline
#define BM 128
#define BN 128
#define BK 32
#define SA 40          // A row stride (bf16): 32 data + 8 pad -> 80B, ldsm conflict-free
#define SB 136         // B row stride (bf16): 128 + 8 pad -> 272B, ldsm.trans conflict-free
#define NSTAGE 3
#define NIT (CH / BK)  // 16
#define AOFF (uint32_t)(BM * SA * 2)   // bytes per A stage per array (10240)
#define BOFF (uint32_t)(BK * SB * 2)   // bytes per B stage per array (8704)
#define SMEM_G (size_t)(NSTAGE * (2 * BM * SA + 2 * BK * SB) * 2)   // 113664 B

// ---------------------------------------------------------------------------
// Scratch (device globals — no allocation allowed)
// g_kqv: fused fp32 [B][1536][4096]; rows 0-511 = k, 512-1023 = q, 1024-1535 = v
// ---------------------------------------------------------------------------
__device__ float g_kqv[(size_t)BATCH * MQKV * HWN];
__device__ float g_ctx[BATCH * NHEADS * HD * HD];
__device__ bf16  g_xh[(size_t)BATCH * CH * HWN];
__device__ bf16  g_xl[(size_t)BATCH * CH * HWN];
__device__ bf16  g_qh[(size_t)BATCH * CH * HWN];
__device__ bf16  g_ql[(size_t)BATCH * CH * HWN];
__device__ bf16  g_wh[MQKV * CH];
__device__ bf16  g_wl[MQKV * CH];
__device__ bf16  g_weffh[(size_t)BATCH * CH * CH];
__device__ bf16  g_weffl[(size_t)BATCH * CH * CH];

// ---------------------------------------------------------------------------
// PTX helpers (sm_80-class only — no tcgen05 on this toolchain target)
// ---------------------------------------------------------------------------
#define CP16(dst_u32, src_ptr) \
    asm volatile("cp.async.cg.shared.global [%0], [%1], 16;\n" :: "r"(dst_u32), "l"(src_ptr))
#define CP_COMMIT() asm volatile("cp.async.commit_group;\n" ::: "memory")
#define CP_WAIT1()  asm volatile("cp.async.wait_group 1;\n"  ::: "memory")

#define LDSM4(R, addr) \
    asm volatile("ldmatrix.sync.aligned.m8n8.x4.shared.b16 {%0,%1,%2,%3}, [%4];" \
        : "=r"((R)[0]), "=r"((R)[1]), "=r"((R)[2]), "=r"((R)[3]) : "r"(addr))

#define LDSM4T(R, addr) \
    asm volatile("ldmatrix.sync.aligned.m8n8.x4.trans.shared.b16 {%0,%1,%2,%3}, [%4];" \
        : "=r"((R)[0]), "=r"((R)[1]), "=r"((R)[2]), "=r"((R)[3]) : "r"(addr))

#define MMA16816(d, a, b0v, b1v) \
    asm volatile("mma.sync.aligned.m16n8k16.row.col.f32.bf16.bf16.f32 " \
        "{%0,%1,%2,%3},{%4,%5,%6,%7},{%8,%9},{%0,%1,%2,%3};" \
        : "+f"((d)[0]), "+f"((d)[1]), "+f"((d)[2]), "+f"((d)[3]) \
        : "r"((a)[0]), "r"((a)[1]), "r"((a)[2]), "r"((a)[3]), "r"(b0v), "r"(b1v))

__device__ __forceinline__ uint32_t smem_u32(const void* p) {
    uint32_t a;
    asm("{ .reg .u64 t; cvta.to.shared.u64 t, %1; cvt.u32.u64 %0, t; }" : "=r"(a) : "l"(p));
    return a;
}

__device__ __forceinline__ void split_f32(float v, bf16& h, bf16& l) {
    h = __float2bfloat16_rn(v);
    l = __float2bfloat16_rn(v - __bfloat162float(h));
}

// ---------------------------------------------------------------------------
// bf16x3 batched GEMM with bias: out[b] = A(b) @ X[b] + bias
// A_hi/A_lo: [Mtot, 512] bf16 row-major (a_bstride per batch; 0 = shared)
// B_hi/B_lo: [512, 4096] bf16 per batch; out fp32.
// 3-stage cp.async pipeline, BK=32, one __syncthreads per slab.
// Accumulates Ah*Bh + Ah*Bl + Al*Bh in fp32.
// ---------------------------------------------------------------------------
__global__ __launch_bounds__(256, 1) void gemm_bf16x3(
    const bf16* __restrict__ Ah, const bf16* __restrict__ Al, long a_bstride,
    const bf16* __restrict__ Bh, const bf16* __restrict__ Bl,
    const float* __restrict__ bias0, const float* __restrict__ bias1,
    const float* __restrict__ bias2,
    long out_bstride, float* __restrict__ out)
{
    extern __shared__ __align__(16) bf16 dsm[];
    const uint32_t sbase = smem_u32(dsm);
    const uint32_t sAh_b = sbase;
    const uint32_t sAl_b = sbase + NSTAGE * AOFF;
    const uint32_t sBh_b = sbase + 2 * NSTAGE * AOFF;
    const uint32_t sBl_b = sbase + 2 * NSTAGE * AOFF + NSTAGE * BOFF;

    const int bz = blockIdx.z;
    const int m0 = blockIdx.y * BM;
    const int n0 = blockIdx.x * BN;
    const bf16* Ahg = Ah + (long)bz * a_bstride + (long)m0 * CH;
    const bf16* Alg = Al + (long)bz * a_bstride + (long)m0 * CH;
    const bf16* Bhg = Bh + (long)bz * (long)CH * HWN + n0;
    const bf16* Blg = Bl + (long)bz * (long)CH * HWN + n0;
    out += (long)bz * out_bstride;

    const int t = threadIdx.x, lane = t & 31, wid = t >> 5;
    const int wm = (wid >> 2) * 64;      // warp m-offset (0/64)
    const int wn = (wid & 3) * 32;       // warp n-offset

    // ---- staging lambda-ish macro: stage 'st', k origin 'k0' ----
#define STAGE_ISSUE(st, k0) do {                                                     \
    _Pragma("unroll")                                                                \
    for (int c = 0; c < 4; c++) {                                                    \
        int idx = c * 256 + t;                                                       \
        int arr = idx >> 9;                                                          \
        int a = idx & 511;                                                           \
        int row = a >> 2, kc = a & 3;                                                \
        uint32_t dst = (arr ? sAl_b : sAh_b) + (uint32_t)(st) * AOFF                 \
                     + (uint32_t)(row * SA + kc * 8) * 2;                            \
        const bf16* src = (arr ? Alg : Ahg) + (long)row * CH + (k0) + kc * 8;        \
        CP16(dst, src);                                                              \
    }                                                                                \
    _Pragma("unroll")                                                                \
    for (int c = 0; c < 4; c++) {                                                    \
        int idx = c * 256 + t;                                                       \
        int arr = idx >> 9;                                                          \
        int b2 = idx & 511;                                                          \
        int kr = b2 >> 4, nc = b2 & 15;                                              \
        uint32_t dst = (arr ? sBl_b : sBh_b) + (uint32_t)(st) * BOFF                 \
                     + (uint32_t)(kr * SB + nc * 8) * 2;                             \
        const bf16* src = (arr ? Blg : Bhg) + (long)((k0) + kr) * HWN + nc * 8;      \
        CP16(dst, src);                                                              \
    } } while (0)

    float acc[4][4][4];
#pragma unroll
    for (int i = 0; i < 4; i++)
#pragma unroll
        for (int j = 0; j < 4; j++)
#pragma unroll
            for (int r = 0; r < 4; r++) acc[i][j][r] = 0.f;

    // prologue: stages 0 and 1
    STAGE_ISSUE(0, 0);
    CP_COMMIT();
    STAGE_ISSUE(1, BK);
    CP_COMMIT();

    const int a_row = lane & 15, a_colq = (lane >> 4) * 8;

    int st = 0;
    for (int it = 0; it < NIT; ++it) {
        CP_WAIT1();                 // stage 'it' arrived (<=1 group pending)
        __syncthreads();            // all warps done reading the stage we overwrite

        if (it + 2 < NIT) {
            const int wst = (st + 2 >= NSTAGE) ? (st + 2 - NSTAGE) : (st + 2);
            STAGE_ISSUE(wst, (it + 2) * BK);
        }
        CP_COMMIT();                // always commit (possibly empty group)

        // compute the two k-slices of this slab
#pragma unroll
        for (int ks = 0; ks < 2; ks++) {
            uint32_t ah[4][4], al[4][4], bh[2][4], bl[2][4];
#pragma unroll
            for (int mt = 0; mt < 4; mt++) {
                const uint32_t ao = st * AOFF
                    + (uint32_t)((wm + mt * 16 + a_row) * SA + ks * 16 + a_colq) * 2;
                LDSM4(ah[mt], sAh_b + ao);
                LDSM4(al[mt], sAl_b + ao);
            }
#pragma unroll
            for (int gi = 0; gi < 2; gi++) {
                const uint32_t bo = st * BOFF
                    + (uint32_t)((ks * 16 + a_row) * SB + wn + gi * 16 + a_colq) * 2;
                LDSM4T(bh[gi], sBh_b + bo);
                LDSM4T(bl[gi], sBl_b + bo);
            }
#pragma unroll
            for (int mt = 0; mt < 4; mt++)
#pragma unroll
                for (int nt = 0; nt < 4; nt++) {
                    const int gi = nt >> 1, p = (nt & 1) * 2;
                    MMA16816(acc[mt][nt], ah[mt], bh[gi][p], bh[gi][p + 1]);
                    MMA16816(acc[mt][nt], ah[mt], bl[gi][p], bl[gi][p + 1]);
                    MMA16816(acc[mt][nt], al[mt], bh[gi][p], bh[gi][p + 1]);
                }
        }
        st = (st + 1 >= NSTAGE) ? 0 : st + 1;
    }

    // ---- epilogue: per-section bias + fp32 store ----
    const int gq = lane >> 2, tq = lane & 3;
#pragma unroll
    for (int mt = 0; mt < 4; mt++) {
        const int m = m0 + wm + mt * 16 + gq;
        const float* bs = (m < CH) ? bias0 : (m < 2 * CH) ? bias1 : bias2;
        const float b0v = bs[m & (CH - 1)], b1v = bs[(m + 8) & (CH - 1)];
#pragma unroll
        for (int nt = 0; nt < 4; nt++) {
            const int n = n0 + wn + nt * 8 + tq * 2;
            float2 v0 = make_float2(acc[mt][nt][0] + b0v, acc[mt][nt][1] + b0v);
            float2 v1 = make_float2(acc[mt][nt][2] + b1v, acc[mt][nt][3] + b1v);
            *reinterpret_cast<float2*>(&out[(long)m * HWN + n]) = v0;
            *reinterpret_cast<float2*>(&out[(long)(m + 8) * HWN + n]) = v1;
        }
    }
#undef STAGE_ISSUE
}

// ---------------------------------------------------------------------------
// fp32 -> bf16 hi/lo split (float4 per thread)
// ---------------------------------------------------------------------------
__global__ __launch_bounds__(256) void split_kernel(
    const float* __restrict__ in, bf16* __restrict__ hi, bf16* __restrict__ lo, int n4)
{
    const int i = blockIdx.x * 256 + threadIdx.x;
    if (i >= n4) return;
    float4 v = reinterpret_cast<const float4*>(in)[i];
    bf16 h0, h1, h2, h3, l0, l1, l2, l3;
    split_f32(v.x, h0, l0);
    split_f32(v.y, h1, l1);
    split_f32(v.z, h2, l2);
    split_f32(v.w, h3, l3);
    __nv_bfloat162* hp = reinterpret_cast<__nv_bfloat162*>(hi) + 2 * i;
    __nv_bfloat162* lp = reinterpret_cast<__nv_bfloat162*>(lo) + 2 * i;
    hp[0] = __nv_bfloat162(h0, h1);
    hp[1] = __nv_bfloat162(h2, h3);
    lp[0] = __nv_bfloat162(l0, l1);
    lp[1] = __nv_bfloat162(l2, l3);
}

// ---------------------------------------------------------------------------
// Softmax over the spatial axis (4096) for the k section of g_kqv.
// ---------------------------------------------------------------------------
__global__ __launch_bounds__(256) void softmax_spatial()
{
    const int b = blockIdx.x >> 9;
    const int c = blockIdx.x & (CH - 1);
    float* p = g_kqv + ((long)b * MQKV + c) * HWN;
    const int t = threadIdx.x;

    __shared__ float redmax[8];
    __shared__ float redsum[8];

    float vals[16];
    float mx = -1e30f;
#pragma unroll
    for (int i = 0; i < 16; i++) {
        vals[i] = p[t + 256 * i];
        mx = fmaxf(mx, vals[i]);
    }
#pragma unroll
    for (int off = 16; off; off >>= 1)
        mx = fmaxf(mx, __shfl_xor_sync(0xffffffffu, mx, off));
    if ((t & 31) == 0) redmax[t >> 5] = mx;
    __syncthreads();
    float bm = redmax[0];
#pragma unroll
    for (int w = 1; w < 8; w++) bm = fmaxf(bm, redmax[w]);

    float s = 0.f;
#pragma unroll
    for (int i = 0; i < 16; i++) {
        vals[i] = __expf(vals[i] - bm);
        s += vals[i];
    }
#pragma unroll
    for (int off = 16; off; off >>= 1)
        s += __shfl_xor_sync(0xffffffffu, s, off);
    if ((t & 31) == 0) redsum[t >> 5] = s;
    __syncthreads();
    float tot = 0.f;
#pragma unroll
    for (int w = 0; w < 8; w++) tot += redsum[w];
    const float inv = 1.f / tot;

#pragma unroll
    for (int i = 0; i < 16; i++)
        p[t + 256 * i] = vals[i] * inv;
}

// ---------------------------------------------------------------------------
// Per-head channel softmax (64) for the q section; emits bf16 hi/lo split.
// ---------------------------------------------------------------------------
__global__ __launch_bounds__(256) void softmax_channel_split(
    bf16* __restrict__ qh, bf16* __restrict__ ql)
{
    const int idx = blockIdx.x * 256 + threadIdx.x;   // B * NHEADS * HWN
    const int l  = idx & (HWN - 1);
    const int bh = idx >> 12;
    const int h  = bh & (NHEADS - 1);
    const int b  = bh >> 3;
    const float* src = g_kqv + ((long)b * MQKV + CH + (long)h * HD) * HWN + l;
    const long dst = ((long)b * CH + (long)h * HD) * HWN + l;

    float v[HD];
    float mx = -1e30f;
#pragma unroll
    for (int c = 0; c < HD; c++) {
        v[c] = src[(long)c * HWN];
        mx = fmaxf(mx, v[c]);
    }
    float s = 0.f;
#pragma unroll
    for (int c = 0; c < HD; c++) {
        v[c] = __expf(v[c] - mx);
        s += v[c];
    }
    const float inv = 1.f / s;
#pragma unroll
    for (int c = 0; c < HD; c++) {
        bf16 hh, ll;
        split_f32(v[c] * inv, hh, ll);
        qh[dst + (long)c * HWN] = hh;
        ql[dst + (long)c * HWN] = ll;
    }
}

// ---------------------------------------------------------------------------
// ctx[b,h] = k_soft[b,h] @ v[b,h]^T : [64,4096] x [64,4096]^T -> [64,64]
// ---------------------------------------------------------------------------
__global__ __launch_bounds__(256) void ctx_kernel()
{
    const int bh = blockIdx.x;
    const int b = bh >> 3, h = bh & (NHEADS - 1);
    const float* kp = g_kqv + ((long)b * MQKV + (long)h * HD) * HWN;
    const float* vp = g_kqv + ((long)b * MQKV + 2 * CH + (long)h * HD) * HWN;

    __shared__ float ks[64][65];
    __shared__ float vs[64][65];

    const int t  = threadIdx.x;
    const int tx = t & 15, ty = t >> 4;
    float acc[4][4] = {};

    for (int l0 = 0; l0 < HWN; l0 += 64) {
#pragma unroll
        for (int r = 0; r < 16; r++) {
            const int idx = t + r * 256;
            const int row = idx >> 6, col = idx & 63;
            ks[row][col] = kp[(long)row * HWN + l0 + col];
            vs[row][col] = vp[(long)row * HWN + l0 + col];
        }
        __syncthreads();
#pragma unroll
        for (int ll = 0; ll < 64; ll++) {
            float a[4], bb[4];
#pragma unroll
            for (int i = 0; i < 4; i++) a[i] = ks[ty * 4 + i][ll];
#pragma unroll
            for (int j = 0; j < 4; j++) bb[j] = vs[tx * 4 + j][ll];
#pragma unroll
            for (int i = 0; i < 4; i++)
#pragma unroll
                for (int j = 0; j < 4; j++)
                    acc[i][j] += a[i] * bb[j];
        }
        __syncthreads();
    }

    float* cp = g_ctx + (long)bh * HD * HD;
#pragma unroll
    for (int i = 0; i < 4; i++)
#pragma unroll
        for (int j = 0; j < 4; j++)
            cp[(ty * 4 + i) * HD + tx * 4 + j] = acc[i][j];
}

// ---------------------------------------------------------------------------
// Weff[b][o][h*64+k] = sum_v Wr[o, h*64+v] * ctx[b,h,k,v] -> bf16 hi/lo
// ---------------------------------------------------------------------------
__global__ __launch_bounds__(256) void weff_split(const float* __restrict__ Wr)
{
    const int idx = blockIdx.x * 256 + threadIdx.x;
    const int col = idx & (CH - 1);
    const int o   = (idx >> 9) & (CH - 1);
    const int b   = idx >> 18;
    const int h   = col >> 6;
    const int kk  = col & 63;

    const float* wr = Wr + (long)o * CH + h * HD;
    const float* cx = g_ctx + ((long)(b * NHEADS + h) * HD + kk) * HD;
    float s = 0.f;
#pragma unroll
    for (int vv = 0; vv < HD; vv++)
        s += wr[vv] * cx[vv];
    bf16 hh, ll;
    split_f32(s, hh, ll);
    g_weffh[idx] = hh;
    g_weffl[idx] = ll;
}

// ---------------------------------------------------------------------------
extern "C" void kernel_launch(void* const* d_in, const int* in_sizes, int n_in,
                              void* d_out, int out_size)
{
    const float* x  = (const float*)d_in[0];
    const float* Wk = (const float*)d_in[1];
    const float* bk = (const float*)d_in[2];
    const float* Wq = (const float*)d_in[3];
    const float* bq = (const float*)d_in[4];
    const float* Wv = (const float*)d_in[5];
    const float* bv = (const float*)d_in[6];
    const float* Wr = (const float*)d_in[7];
    const float* br = (const float*)d_in[8];
    float* out = (float*)d_out;

    float* pkqv;
    bf16 *pxh, *pxl, *pqh, *pql, *pwh, *pwl, *pweh, *pwel;
    cudaGetSymbolAddress((void**)&pkqv, g_kqv);
    cudaGetSymbolAddress((void**)&pxh,  g_xh);
    cudaGetSymbolAddress((void**)&pxl,  g_xl);
    cudaGetSymbolAddress((void**)&pqh,  g_qh);
    cudaGetSymbolAddress((void**)&pql,  g_ql);
    cudaGetSymbolAddress((void**)&pwh,  g_wh);
    cudaGetSymbolAddress((void**)&pwl,  g_wl);
    cudaGetSymbolAddress((void**)&pweh, g_weffh);
    cudaGetSymbolAddress((void**)&pwel, g_weffl);

    cudaFuncSetAttribute(gemm_bf16x3, cudaFuncAttributeMaxDynamicSharedMemorySize,
                         (int)SMEM_G);

    const int WN4 = CH * CH / 4;
    const int XN4 = BATCH * CH * HWN / 4;

    // Split weights (stacked [Wk;Wq;Wv]) and x into bf16 hi/lo
    split_kernel<<<WN4 / 256, 256>>>(Wk, pwh + 0 * CH * CH, pwl + 0 * CH * CH, WN4);
    split_kernel<<<WN4 / 256, 256>>>(Wq, pwh + 1 * CH * CH, pwl + 1 * CH * CH, WN4);
    split_kernel<<<WN4 / 256, 256>>>(Wv, pwh + 2 * CH * CH, pwl + 2 * CH * CH, WN4);
    split_kernel<<<XN4 / 256, 256>>>(x, pxh, pxl, XN4);

    // Fused QKV projection: [1536,512] @ [512,4096] per batch (x read once)
    dim3 qkv_grid(HWN / BN, MQKV / BM, BATCH);
    gemm_bf16x3<<<qkv_grid, 256, SMEM_G>>>(pwh, pwl, 0, pxh, pxl,
                                           bk, bq, bv, (long)MQKV * HWN, pkqv);

    // Softmaxes
    softmax_spatial<<<BATCH * CH, 256>>>();
    softmax_channel_split<<<(BATCH * NHEADS * HWN) / 256, 256>>>(pqh, pql);

    // ctx = k @ v^T per (b, h)
    ctx_kernel<<<BATCH * NHEADS, 256>>>();

    // Fold Wr through ctx -> per-batch effective weight (bf16 hi/lo)
    weff_split<<<(BATCH * CH * CH) / 256, 256>>>(Wr);

    // out[b] = Weff[b] @ q[b] + br
    dim3 out_grid(HWN / BN, CH / BM, BATCH);
    gemm_bf16x3<<<out_grid, 256, SMEM_G>>>(pweh, pwel, (long)CH * CH, pqh, pql,
                                           br, br, br, (long)CH * HWN, out);
}